// round 15
// baseline (speedup 1.0000x reference)
#include <cuda_runtime.h>
#include <cuda_bf16.h>
#include <math.h>
#include <stdint.h>

#define Bb   1024
#define Tt   32
#define Xs   128
#define XHd  512
#define AHd  512
#define Dd   1152
#define G3   1536
#define NSTEP 31

typedef __nv_bfloat16 bf16;
typedef __nv_bfloat162 bf162;

// ---------------- fp32 scratch ----------------
__device__ float g_s   [Bb * Dd];
__device__ float g_mask[Bb];
__device__ float g_gia [Bb * G3];
__device__ float g_gha [Bb * G3];
__device__ float g_gix [Bb * G3];
__device__ float g_ghx [Bb * G3];
__device__ float g_k1  [Bb * Dd];
__device__ float g_k2  [Bb * Dd];
__device__ float g_k3  [Bb * Dd];
__device__ float g_k4  [Bb * Dd];
__device__ float g_accb[Bb * Dd];

// ---------------- packed bf16 (A-side [hi|hi|lo], B-side [hi|lo|hi]) -----
__device__ bf16 pk_s  [Bb * 3 * Dd];
__device__ bf16 pk_cat[Bb * 3 * 256];
__device__ bf16 pk_h  [Bb * 3 * Dd];
__device__ bf16 pw_iha[G3 * 3 * 256];
__device__ bf16 pw_hha[G3 * 3 * 512];
__device__ bf16 pw_ihx[G3 * 3 * 128];
__device__ bf16 pw_hhx[G3 * 3 * 512];
__device__ bf16 pw_1  [Dd * 3 * Dd];
__device__ bf16 pw_2  [Dd * 3 * Dd];

__device__ __forceinline__ float sigm(float x) { return 1.0f / (1.0f + expf(-x)); }
__device__ __forceinline__ float splus(float x) { return fmaxf(x, 0.f) + log1pf(expf(-fabsf(x))); }

__device__ __forceinline__ void packA_el(bf16* rowbase, int K, int k, float v)
{
    bf16 hi = __float2bfloat16(v);
    bf16 lo = __float2bfloat16(v - __bfloat162float(hi));
    rowbase[k] = hi; rowbase[K + k] = hi; rowbase[2 * K + k] = lo;
}

__device__ __forceinline__ void cpa16(uint32_t sa, const void* g)
{
    asm volatile("cp.async.cg.shared.global [%0], [%1], 16;\n" :: "r"(sa), "l"(g));
}

#define SSTR 15360
#define SMEM_SZ (4 * SSTR)

// ======== gates GEMM: 128 threads, 4 warps, 64x32 warp tiles =============
// Same block tile BM=64 BN=128 BK=32 and identical per-output K-chains as the
// 8-warp version — only warp->output mapping changed (validated on dgemm).
struct Cfg {
    const bf16 *A, *B;
    const float *bias;
    void *Cv;
    int lda, segA, ldb, segB, ldc, K, mode;
};
struct Cfg4 { Cfg c[4]; };

__global__ void __launch_bounds__(128) gemm_bf16(Cfg4 P)
{
    const Cfg cg = P.c[blockIdx.z];
    const bf16* __restrict__ A = cg.A;
    const bf16* __restrict__ B = cg.B;
    const int lda = cg.lda, segA = cg.segA, ldb = cg.ldb, segB = cg.segB;
    const int K = cg.K;
    const int nk = 3 * K / 32;

    extern __shared__ __align__(16) char smraw[];
    const uint32_t su = (uint32_t)__cvta_generic_to_shared(smraw);

    const int tid = threadIdx.x, lane = tid & 31;
    const int wn = tid >> 5;                 // 0..3
    const int bm = blockIdx.y, bn = blockIdx.x;

    const int arow = tid >> 2, ac8 = (tid & 3) * 8;   // 32 rows x 4 chunks
    const bf16* Ag = A + (size_t)(bm * 64 + arow) * lda;
    const bf16* Bg = B + (size_t)(bn * 128 + arow) * ldb;

    float acc[4][4][4];
#pragma unroll
    for (int i = 0; i < 4; i++)
#pragma unroll
        for (int j = 0; j < 4; j++)
#pragma unroll
            for (int q = 0; q < 4; q++) acc[i][j][q] = 0.f;

#define ISSUE_G(I)                                                             \
    {                                                                          \
        int kk = (I) * 32;                                                     \
        int seg = (kk >= K) ? ((kk >= 2 * K) ? 2 : 1) : 0;                     \
        int w = kk - seg * K;                                                  \
        int acl = seg * segA + w;                                              \
        int bcl = seg * segB + w;                                              \
        uint32_t sb = su + ((I) & 3) * SSTR;                                   \
        _Pragma("unroll")                                                      \
        for (int p = 0; p < 2; p++)                                            \
            cpa16(sb + (p * 32 + arow) * 80 + ac8 * 2,                         \
                  Ag + (size_t)(p * 32) * lda + acl + ac8);                    \
        _Pragma("unroll")                                                      \
        for (int p = 0; p < 4; p++)                                            \
            cpa16(sb + 5120 + (p * 32 + arow) * 80 + ac8 * 2,                  \
                  Bg + (size_t)(p * 32) * ldb + bcl + ac8);                    \
        asm volatile("cp.async.commit_group;\n" ::);                           \
    }

#define COMPUTE_G(I)                                                           \
    {                                                                          \
        const uint32_t sa_base = su + ((I) & 3) * SSTR;                        \
        const uint32_t sb_base = sa_base + 5120;                               \
        _Pragma("unroll")                                                      \
        for (int ks = 0; ks < 2; ks++) {                                       \
            const int k0 = ks * 16;                                            \
            uint32_t a[4][4], b[4][2];                                         \
            _Pragma("unroll")                                                  \
            for (int mi = 0; mi < 4; mi++) {                                   \
                uint32_t sa = sa_base + (mi * 16 + (lane & 15)) * 80           \
                            + (k0 + (lane >> 4) * 8) * 2;                      \
                asm volatile(                                                  \
                    "ldmatrix.sync.aligned.m8n8.x4.shared.b16 {%0,%1,%2,%3}, [%4];" \
                    : "=r"(a[mi][0]), "=r"(a[mi][1]), "=r"(a[mi][2]), "=r"(a[mi][3]) \
                    : "r"(sa));                                                \
            }                                                                  \
            _Pragma("unroll")                                                  \
            for (int p = 0; p < 2; p++) {                                      \
                uint32_t sb = sb_base                                          \
                    + (wn * 32 + (2 * p + ((lane >> 4) & 1)) * 8 + (lane & 7)) * 80 \
                    + (k0 + ((lane >> 3) & 1) * 8) * 2;                        \
                asm volatile(                                                  \
                    "ldmatrix.sync.aligned.m8n8.x4.shared.b16 {%0,%1,%2,%3}, [%4];" \
                    : "=r"(b[2 * p][0]), "=r"(b[2 * p][1]),                    \
                      "=r"(b[2 * p + 1][0]), "=r"(b[2 * p + 1][1])             \
                    : "r"(sb));                                                \
            }                                                                  \
            _Pragma("unroll")                                                  \
            for (int mi = 0; mi < 4; mi++)                                     \
                _Pragma("unroll")                                              \
                for (int ni = 0; ni < 4; ni++) {                               \
                    asm volatile(                                              \
                        "mma.sync.aligned.m16n8k16.row.col.f32.bf16.bf16.f32 " \
                        "{%0,%1,%2,%3}, {%4,%5,%6,%7}, {%8,%9}, {%0,%1,%2,%3};"\
                        : "+f"(acc[mi][ni][0]), "+f"(acc[mi][ni][1]),          \
                          "+f"(acc[mi][ni][2]), "+f"(acc[mi][ni][3])           \
                        : "r"(a[mi][0]), "r"(a[mi][1]), "r"(a[mi][2]), "r"(a[mi][3]), \
                          "r"(b[ni][0]), "r"(b[ni][1]));                       \
                }                                                              \
        }                                                                      \
    }

    ISSUE_G(0) ISSUE_G(1) ISSUE_G(2)

    for (int i = 0; i < nk; i++) {
        const int rem = nk - 1 - i;
        if (rem >= 2)      asm volatile("cp.async.wait_group 2;\n" ::);
        else if (rem == 1) asm volatile("cp.async.wait_group 1;\n" ::);
        else               asm volatile("cp.async.wait_group 0;\n" ::);
        __syncthreads();
        if (i + 3 < nk) ISSUE_G(i + 3)
        COMPUTE_G(i)
    }
#undef ISSUE_G
#undef COMPUTE_G

    const int cbase = bn * 128 + wn * 32;
    const float* bias = cg.bias;
    float* C = (float*)cg.Cv;
    const int ldc = cg.ldc;
#pragma unroll
    for (int mi = 0; mi < 4; mi++)
#pragma unroll
        for (int ni = 0; ni < 4; ni++) {
            int r0 = bm * 64 + mi * 16 + (lane >> 2);
            int c0 = cbase + ni * 8 + (lane & 3) * 2;
            float b0 = bias[c0], b1 = bias[c0 + 1];
            float2 o0 = make_float2(acc[mi][ni][0] + b0, acc[mi][ni][1] + b1);
            float2 o1 = make_float2(acc[mi][ni][2] + b0, acc[mi][ni][3] + b1);
            *(float2*)(C + (size_t)r0 * ldc + c0) = o0;
            *(float2*)(C + (size_t)(r0 + 8) * ldc + c0) = o1;
        }
}

// ====== specialized D-GEMM (R14, unchanged): 128 thr, 64x32 warp tiles ===
template <int MODE>
__global__ void __launch_bounds__(128) dgemm(
    const bf16* __restrict__ A, const bf16* __restrict__ B,
    const float* __restrict__ bias, void* __restrict__ Cv, int ldc)
{
    constexpr int K = 1152, LD = 3456, NK = 108;

    extern __shared__ __align__(16) char smraw[];
    const uint32_t su = (uint32_t)__cvta_generic_to_shared(smraw);

    const int tid = threadIdx.x, lane = tid & 31;
    const int wn = tid >> 5;
    const int bm = blockIdx.y, bn = blockIdx.x;

    const int arow = tid >> 2, ac8 = (tid & 3) * 8;
    const bf16* Ag = A + (size_t)(bm * 64 + arow) * LD + ac8;
    const bf16* Bg = B + (size_t)(bn * 128 + arow) * LD + ac8;

    float acc[4][4][4];
#pragma unroll
    for (int i = 0; i < 4; i++)
#pragma unroll
        for (int j = 0; j < 4; j++)
#pragma unroll
            for (int q = 0; q < 4; q++) acc[i][j][q] = 0.f;

#define ISSUE_D(I)                                                             \
    {                                                                          \
        int kk = (I) * 32;                                                     \
        uint32_t sb = su + ((I) & 3) * SSTR;                                   \
        _Pragma("unroll")                                                      \
        for (int p = 0; p < 2; p++)                                            \
            cpa16(sb + (p * 32 + arow) * 80 + ac8 * 2,                         \
                  Ag + (size_t)(p * 32) * LD + kk);                            \
        _Pragma("unroll")                                                      \
        for (int p = 0; p < 4; p++)                                            \
            cpa16(sb + 5120 + (p * 32 + arow) * 80 + ac8 * 2,                  \
                  Bg + (size_t)(p * 32) * LD + kk);                            \
        asm volatile("cp.async.commit_group;\n" ::);                           \
    }

#define COMPUTE_D(I)                                                           \
    {                                                                          \
        const uint32_t sa_base = su + ((I) & 3) * SSTR;                        \
        const uint32_t sb_base = sa_base + 5120;                               \
        _Pragma("unroll")                                                      \
        for (int ks = 0; ks < 2; ks++) {                                       \
            const int k0 = ks * 16;                                            \
            uint32_t a[4][4], b[4][2];                                         \
            _Pragma("unroll")                                                  \
            for (int mi = 0; mi < 4; mi++) {                                   \
                uint32_t sa = sa_base + (mi * 16 + (lane & 15)) * 80           \
                            + (k0 + (lane >> 4) * 8) * 2;                      \
                asm volatile(                                                  \
                    "ldmatrix.sync.aligned.m8n8.x4.shared.b16 {%0,%1,%2,%3}, [%4];" \
                    : "=r"(a[mi][0]), "=r"(a[mi][1]), "=r"(a[mi][2]), "=r"(a[mi][3]) \
                    : "r"(sa));                                                \
            }                                                                  \
            _Pragma("unroll")                                                  \
            for (int p = 0; p < 2; p++) {                                      \
                uint32_t sb = sb_base                                          \
                    + (wn * 32 + (2 * p + ((lane >> 4) & 1)) * 8 + (lane & 7)) * 80 \
                    + (k0 + ((lane >> 3) & 1) * 8) * 2;                        \
                asm volatile(                                                  \
                    "ldmatrix.sync.aligned.m8n8.x4.shared.b16 {%0,%1,%2,%3}, [%4];" \
                    : "=r"(b[2 * p][0]), "=r"(b[2 * p][1]),                    \
                      "=r"(b[2 * p + 1][0]), "=r"(b[2 * p + 1][1])             \
                    : "r"(sb));                                                \
            }                                                                  \
            _Pragma("unroll")                                                  \
            for (int mi = 0; mi < 4; mi++)                                     \
                _Pragma("unroll")                                              \
                for (int ni = 0; ni < 4; ni++) {                               \
                    asm volatile(                                              \
                        "mma.sync.aligned.m16n8k16.row.col.f32.bf16.bf16.f32 " \
                        "{%0,%1,%2,%3}, {%4,%5,%6,%7}, {%8,%9}, {%0,%1,%2,%3};"\
                        : "+f"(acc[mi][ni][0]), "+f"(acc[mi][ni][1]),          \
                          "+f"(acc[mi][ni][2]), "+f"(acc[mi][ni][3])           \
                        : "r"(a[mi][0]), "r"(a[mi][1]), "r"(a[mi][2]), "r"(a[mi][3]), \
                          "r"(b[ni][0]), "r"(b[ni][1]));                       \
                }                                                              \
        }                                                                      \
    }

    ISSUE_D(0) ISSUE_D(1) ISSUE_D(2)

#pragma unroll 4
    for (int i = 0; i < NK - 3; i++) {
        asm volatile("cp.async.wait_group 2;\n" ::);
        __syncthreads();
        ISSUE_D(i + 3)
        COMPUTE_D(i)
    }
    asm volatile("cp.async.wait_group 2;\n" ::);
    __syncthreads();
    COMPUTE_D(NK - 3)
    asm volatile("cp.async.wait_group 1;\n" ::);
    __syncthreads();
    COMPUTE_D(NK - 2)
    asm volatile("cp.async.wait_group 0;\n" ::);
    __syncthreads();
    COMPUTE_D(NK - 1)

#undef ISSUE_D
#undef COMPUTE_D

    const int cbase = bn * 128 + wn * 32;

    if (MODE == 0) {
        float* C = (float*)Cv;
#pragma unroll
        for (int mi = 0; mi < 4; mi++)
#pragma unroll
            for (int ni = 0; ni < 4; ni++) {
                int r0 = bm * 64 + mi * 16 + (lane >> 2);
                int c0 = cbase + ni * 8 + (lane & 3) * 2;
                float b0 = bias[c0], b1 = bias[c0 + 1];
                float2 o0 = make_float2(acc[mi][ni][0] + b0, acc[mi][ni][1] + b1);
                float2 o1 = make_float2(acc[mi][ni][2] + b0, acc[mi][ni][3] + b1);
                *(float2*)(C + (size_t)r0 * ldc + c0) = o0;
                *(float2*)(C + (size_t)(r0 + 8) * ldc + c0) = o1;
            }
    } else {
        bf16* C = (bf16*)Cv;  // packed, row stride 3456
#pragma unroll
        for (int mi = 0; mi < 4; mi++)
#pragma unroll
            for (int ni = 0; ni < 4; ni++) {
                int r0 = bm * 64 + mi * 16 + (lane >> 2);
                int c0 = cbase + ni * 8 + (lane & 3) * 2;
                float b0 = bias[c0], b1 = bias[c0 + 1];
#pragma unroll
                for (int h = 0; h < 2; h++) {
                    float v0 = splus(acc[mi][ni][2 * h + 0] + b0);
                    float v1 = splus(acc[mi][ni][2 * h + 1] + b1);
                    bf16 h0 = __float2bfloat16(v0), h1 = __float2bfloat16(v1);
                    bf16 l0 = __float2bfloat16(v0 - __bfloat162float(h0));
                    bf16 l1 = __float2bfloat16(v1 - __bfloat162float(h1));
                    bf162 hh; hh.x = h0; hh.y = h1;
                    bf162 ll; ll.x = l0; ll.y = l1;
                    bf16* base = C + (size_t)(r0 + 8 * h) * 3456 + c0;
                    *(bf162*)(base)         = hh;
                    *(bf162*)(base + K)     = hh;
                    *(bf162*)(base + 2 * K) = ll;
                }
            }
    }
}

// ---------------- single fused weight pack (B-side: [hi | lo | hi]) ------
__device__ __forceinline__ void packW_el(const float* in, bf16* out, int idx, int K)
{
    int n = idx / K, k = idx % K;
    float v = in[(size_t)n * K + k];
    bf16 hi = __float2bfloat16(v);
    bf16 lo = __float2bfloat16(v - __bfloat162float(hi));
    bf16* o = out + (size_t)n * 3 * K;
    o[k] = hi; o[K + k] = lo; o[2 * K + k] = hi;
}

#define S0 (G3 * 256)
#define S1B (S0 + G3 * 512)
#define S2B (S1B + G3 * 128)
#define S3B (S2B + G3 * 512)
#define S4B (S3B + Dd * Dd)
#define S5B (S4B + Dd * Dd)

__global__ void packAll_k(const float* __restrict__ Wiha, const float* __restrict__ Whha,
                          const float* __restrict__ Wihx, const float* __restrict__ Whhx,
                          const float* __restrict__ W1,   const float* __restrict__ W2)
{
    int idx = blockIdx.x * blockDim.x + threadIdx.x;
    if (idx >= S5B) return;
    if (idx < S0)       packW_el(Wiha, pw_iha, idx,        256);
    else if (idx < S1B) packW_el(Whha, pw_hha, idx - S0,   512);
    else if (idx < S2B) packW_el(Wihx, pw_ihx, idx - S1B,  128);
    else if (idx < S3B) packW_el(Whhx, pw_hhx, idx - S2B,  512);
    else if (idx < S4B) packW_el(W1,   pw_1,   idx - S3B,  Dd);
    else                packW_el(W2,   pw_2,   idx - S4B,  Dd);
}

// ---------------- elementwise (fused state packing) ----------------
__global__ void init_k(const float* __restrict__ x, float* __restrict__ out_x,
                       float* __restrict__ out_za)
{
    int idx = blockIdx.x * blockDim.x + threadIdx.x;
    if (idx >= Bb * Dd) return;
    int b = idx / Dd, j = idx % Dd;
    float v;
    if (j < 1024) {
        v = 0.0f;
        if (j < AHd) out_za[((size_t)b * Tt) * AHd + j] = 0.0f;
    } else {
        v = x[((size_t)b * Tt) * Xs + (j - 1024)];
        out_x[((size_t)b * Tt) * Xs + (j - 1024)] = v;
    }
    g_s[idx] = v;
    packA_el(pk_s + (size_t)b * 3 * Dd, Dd, j, v);
}

__global__ void catmask_k(const float* __restrict__ y, int t)
{
    int b = blockIdx.x;
    int c = threadIdx.x;  // 128
    float yv = y[((size_t)b * Tt + t) * 128 + c];
    float xv = g_s[b * Dd + 1024 + c];
    bf16* rb = pk_cat + (size_t)b * 768;
    packA_el(rb, 256, c, xv);
    packA_el(rb, 256, 128 + c, yv);
    __shared__ float red[128];
    red[c] = yv;
    __syncthreads();
    for (int o = 64; o > 0; o >>= 1) {
        if (c < o) red[c] += red[c + o];
        __syncthreads();
    }
    if (c == 0) g_mask[b] = (red[0] != 0.0f) ? 1.0f : 0.0f;
}

__global__ void gru_k(float* __restrict__ out_za, int t)
{
    int idx = blockIdx.x * blockDim.x + threadIdx.x;
    if (idx >= Bb * 1024) return;
    int b = idx >> 10, j = idx & 1023;
    if (j < XHd) {
        const float* gi = g_gix + (size_t)b * G3;
        const float* gh = g_ghx + (size_t)b * G3;
        float r = sigm(gi[j] + gh[j]);
        float z = sigm(gi[XHd + j] + gh[XHd + j]);
        float n = tanhf(gi[2 * XHd + j] + r * gh[2 * XHd + j]);
        float h = g_s[b * Dd + j];
        float v = (1.0f - z) * n + z * h;
        g_s[b * Dd + j] = v;
        packA_el(pk_s + (size_t)b * 3 * Dd, Dd, j, v);
    } else {
        int ja = j - XHd;
        const float* gi = g_gia + (size_t)b * G3;
        const float* gh = g_gha + (size_t)b * G3;
        float r = sigm(gi[ja] + gh[ja]);
        float z = sigm(gi[AHd + ja] + gh[AHd + ja]);
        float n = tanhf(gi[2 * AHd + ja] + r * gh[2 * AHd + ja]);
        float h = g_s[b * Dd + XHd + ja];
        float hn = (1.0f - z) * n + z * h;
        float v = (g_mask[b] != 0.0f) ? hn : h;
        g_s[b * Dd + XHd + ja] = v;
        packA_el(pk_s + (size_t)b * 3 * Dd, Dd, XHd + ja, v);
        out_za[((size_t)b * Tt + t + 1) * AHd + ja] = v;
    }
}

__global__ void rk_c1(const float* __restrict__ ts, int t)
{
    int i = blockIdx.x * blockDim.x + threadIdx.x;
    if (i >= Bb * Dd) return;
    float dt = ts[t + 1] - ts[t];
    int b = i / Dd, j = i % Dd;
    float v = g_s[i] + (dt * (1.0f / 3.0f)) * g_k1[i];
    packA_el(pk_s + (size_t)b * 3 * Dd, Dd, j, v);
}
__global__ void rk_c2(const float* __restrict__ ts, int t)
{
    int i = blockIdx.x * blockDim.x + threadIdx.x;
    if (i >= Bb * Dd) return;
    float dt = ts[t + 1] - ts[t];
    int b = i / Dd, j = i % Dd;
    float k1 = g_k1[i], k2 = g_k2[i];
    float v = g_s[i] + dt * (k2 - k1 * (1.0f / 3.0f));
    g_accb[i] = k1 + 3.0f * k2;
    packA_el(pk_s + (size_t)b * 3 * Dd, Dd, j, v);
}
__global__ void rk_c3(const float* __restrict__ ts, int t)
{
    int i = blockIdx.x * blockDim.x + threadIdx.x;
    if (i >= Bb * Dd) return;
    float dt = ts[t + 1] - ts[t];
    int b = i / Dd, j = i % Dd;
    float k1 = g_k1[i], k2 = g_k2[i], k3 = g_k3[i];
    float v = g_s[i] + dt * (k1 - k2 + k3);
    g_accb[i] = g_accb[i] + 3.0f * k3;
    packA_el(pk_s + (size_t)b * 3 * Dd, Dd, j, v);
}
__global__ void rk_c4(const float* __restrict__ ts, float* __restrict__ out_x, int t)
{
    int i = blockIdx.x * blockDim.x + threadIdx.x;
    if (i >= Bb * Dd) return;
    float dt = ts[t + 1] - ts[t];
    int b = i / Dd, j = i % Dd;
    float v = g_s[i] + (dt * 0.125f) * (g_accb[i] + g_k4[i]);
    g_s[i] = v;
    packA_el(pk_s + (size_t)b * 3 * Dd, Dd, j, v);
    if (j >= 1024)
        out_x[((size_t)b * Tt + t + 1) * Xs + (j - 1024)] = v;
}

// ---------------- host ----------------
static inline Cfg mkcfg(const bf16* A, int lda, int segA,
                        const bf16* B, int ldb, int segB,
                        const float* bias, void* C, int ldc, int K, int mode)
{
    Cfg c; c.A = A; c.B = B; c.bias = bias; c.Cv = C;
    c.lda = lda; c.segA = segA; c.ldb = ldb; c.segB = segB;
    c.ldc = ldc; c.K = K; c.mode = mode;
    return c;
}

extern "C" void kernel_launch(void* const* d_in, const int* in_sizes, int n_in,
                              void* d_out, int out_size)
{
    const float* x    = (const float*)d_in[0];
    const float* y    = (const float*)d_in[1];
    const float* ts   = (const float*)d_in[2];
    const float* Wiha = (const float*)d_in[3];
    const float* Whha = (const float*)d_in[4];
    const float* biha = (const float*)d_in[5];
    const float* bhha = (const float*)d_in[6];
    const float* Wihx = (const float*)d_in[7];
    const float* Whhx = (const float*)d_in[8];
    const float* bihx = (const float*)d_in[9];
    const float* bhhx = (const float*)d_in[10];
    const float* W1   = (const float*)d_in[11];
    const float* b1   = (const float*)d_in[12];
    const float* W2   = (const float*)d_in[13];
    const float* b2   = (const float*)d_in[14];

    float* out_x  = (float*)d_out;
    float* out_za = out_x + (size_t)Bb * Tt * Xs;

    cudaFuncSetAttribute(gemm_bf16, cudaFuncAttributeMaxDynamicSharedMemorySize, SMEM_SZ);
    cudaFuncSetAttribute(dgemm<0>,  cudaFuncAttributeMaxDynamicSharedMemorySize, SMEM_SZ);
    cudaFuncSetAttribute(dgemm<1>,  cudaFuncAttributeMaxDynamicSharedMemorySize, SMEM_SZ);

    bf16 *p_s, *p_cat, *p_h, *p_iha, *p_hha, *p_ihx, *p_hhx, *p_w1, *p_w2;
    float *pgia, *pgha, *pgix, *pghx, *pk1, *pk2, *pk3, *pk4;
    cudaGetSymbolAddress((void**)&p_s,   pk_s);
    cudaGetSymbolAddress((void**)&p_cat, pk_cat);
    cudaGetSymbolAddress((void**)&p_h,   pk_h);
    cudaGetSymbolAddress((void**)&p_iha, pw_iha);
    cudaGetSymbolAddress((void**)&p_hha, pw_hha);
    cudaGetSymbolAddress((void**)&p_ihx, pw_ihx);
    cudaGetSymbolAddress((void**)&p_hhx, pw_hhx);
    cudaGetSymbolAddress((void**)&p_w1,  pw_1);
    cudaGetSymbolAddress((void**)&p_w2,  pw_2);
    cudaGetSymbolAddress((void**)&pgia,  g_gia);
    cudaGetSymbolAddress((void**)&pgha,  g_gha);
    cudaGetSymbolAddress((void**)&pgix,  g_gix);
    cudaGetSymbolAddress((void**)&pghx,  g_ghx);
    cudaGetSymbolAddress((void**)&pk1,   g_k1);
    cudaGetSymbolAddress((void**)&pk2,   g_k2);
    cudaGetSymbolAddress((void**)&pk3,   g_k3);
    cudaGetSymbolAddress((void**)&pk4,   g_k4);

    packAll_k<<<(S5B + 255) / 256, 256>>>(Wiha, Whha, Wihx, Whhx, W1, W2);

    const int blkBD = (Bb * Dd + 255) / 256;
    const int blkG  = (Bb * 1024 + 255) / 256;

    init_k<<<blkBD, 256>>>(x, out_x, out_za);

    const dim3 gridGate(G3 / 128, Bb / 64, 4);
    const dim3 gridD(Dd / 128, Bb / 64, 1);

    for (int t = 0; t < NSTEP; t++) {
        catmask_k<<<Bb, 128>>>(y, t);

        Cfg4 G;
        G.c[0] = mkcfg(p_s + XHd,   3456, 1152, p_hha, 1536, 512, bhha, pgha, G3, 512, 0);
        G.c[1] = mkcfg(p_s,         3456, 1152, p_hhx, 1536, 512, bhhx, pghx, G3, 512, 0);
        G.c[2] = mkcfg(p_cat,        768, 256,  p_iha, 768,  256, biha, pgia, G3, 256, 0);
        G.c[3] = mkcfg(p_s + 1024,  3456, 1152, p_ihx, 384,  128, bihx, pgix, G3, 128, 0);
        gemm_bf16<<<gridGate, 128, SMEM_SZ>>>(G);

        gru_k<<<blkG, 256>>>(out_za, t);

        float* kouts[4] = {pk1, pk2, pk3, pk4};
        for (int q = 0; q < 4; q++) {
            dgemm<1><<<gridD, 128, SMEM_SZ>>>(p_s, p_w1, b1, p_h, 0);
            dgemm<0><<<gridD, 128, SMEM_SZ>>>(p_h, p_w2, b2, kouts[q], Dd);
            if (q == 0)      rk_c1<<<blkBD, 256>>>(ts, t);
            else if (q == 1) rk_c2<<<blkBD, 256>>>(ts, t);
            else if (q == 2) rk_c3<<<blkBD, 256>>>(ts, t);
            else             rk_c4<<<blkBD, 256>>>(ts, out_x, t);
        }
    }
}

// round 17
// speedup vs baseline: 1.0393x; 1.0393x over previous
#include <cuda_runtime.h>
#include <cuda_bf16.h>
#include <math.h>
#include <stdint.h>

#define Bb   1024
#define Tt   32
#define Xs   128
#define XHd  512
#define AHd  512
#define Dd   1152
#define G3   1536
#define NSTEP 31

typedef __nv_bfloat16 bf16;
typedef __nv_bfloat162 bf162;

// ---------------- fp32 scratch ----------------
__device__ float g_s   [Bb * Dd];
__device__ float g_mask[Bb];
__device__ float g_gia [Bb * G3];
__device__ float g_gha [Bb * G3];
__device__ float g_gix [Bb * G3];
__device__ float g_ghx [Bb * G3];
__device__ float g_k1  [Bb * Dd];
__device__ float g_k2  [Bb * Dd];
__device__ float g_accb[Bb * Dd];
__device__ float g_pa  [Bb * Dd];   // split-K partial 0
__device__ float g_pb  [Bb * Dd];   // split-K partial 1

// ---------------- packed bf16 (A-side [hi|hi|lo], B-side [hi|lo|hi]) -----
__device__ bf16 pk_s  [Bb * 3 * Dd];
__device__ bf16 pk_cat[Bb * 3 * 256];
__device__ bf16 pk_h  [Bb * 3 * Dd];
__device__ bf16 pw_iha[G3 * 3 * 256];
__device__ bf16 pw_hha[G3 * 3 * 512];
__device__ bf16 pw_ihx[G3 * 3 * 128];
__device__ bf16 pw_hhx[G3 * 3 * 512];
__device__ bf16 pw_1  [Dd * 3 * Dd];
__device__ bf16 pw_2  [Dd * 3 * Dd];

__device__ __forceinline__ float sigm(float x) { return 1.0f / (1.0f + expf(-x)); }
__device__ __forceinline__ float splus(float x) { return fmaxf(x, 0.f) + log1pf(expf(-fabsf(x))); }

__device__ __forceinline__ void packA_el(bf16* rowbase, int K, int k, float v)
{
    bf16 hi = __float2bfloat16(v);
    bf16 lo = __float2bfloat16(v - __bfloat162float(hi));
    rowbase[k] = hi; rowbase[K + k] = hi; rowbase[2 * K + k] = lo;
}

__device__ __forceinline__ void cpa16(uint32_t sa, const void* g)
{
    asm volatile("cp.async.cg.shared.global [%0], [%1], 16;\n" :: "r"(sa), "l"(g));
}

#define SSTR 15360
#define SMEM_SZ (4 * SSTR)

// ================= gates GEMM: 256 threads, 8 warps 2x4 (R14-proven) =====
struct Cfg {
    const bf16 *A, *B;
    const float *bias;
    void *Cv;
    int lda, segA, ldb, segB, ldc, K, mode;
};
struct Cfg4 { Cfg c[4]; };

__global__ void __launch_bounds__(256) gemm_bf16(Cfg4 P)
{
    const Cfg cg = P.c[blockIdx.z];
    const bf16* __restrict__ A = cg.A;
    const bf16* __restrict__ B = cg.B;
    const int lda = cg.lda, segA = cg.segA, ldb = cg.ldb, segB = cg.segB;
    const int K = cg.K;
    const int nk = 3 * K / 32;

    extern __shared__ __align__(16) char smraw[];
    const uint32_t su = (uint32_t)__cvta_generic_to_shared(smraw);

    const int tid = threadIdx.x, lane = tid & 31, wid = tid >> 5;
    const int wm = wid >> 2, wn = wid & 3;
    const int bm = blockIdx.y, bn = blockIdx.x;

    const int arow = tid >> 2, ac8 = (tid & 3) * 8;
    const bf16* Ag  = A + (size_t)(bm * 64 + arow) * lda;
    const bf16* Bg0 = B + (size_t)(bn * 128 + arow) * ldb;
    const bf16* Bg1 = B + (size_t)(bn * 128 + 64 + arow) * ldb;

    float acc[2][4][4];
#pragma unroll
    for (int i = 0; i < 2; i++)
#pragma unroll
        for (int j = 0; j < 4; j++)
#pragma unroll
            for (int q = 0; q < 4; q++) acc[i][j][q] = 0.f;

#define ISSUE_G(I)                                                             \
    {                                                                          \
        int kk = (I) * 32;                                                     \
        int seg = (kk >= K) ? ((kk >= 2 * K) ? 2 : 1) : 0;                     \
        int w = kk - seg * K;                                                  \
        int acl = seg * segA + w;                                              \
        int bcl = seg * segB + w;                                              \
        uint32_t sb = su + ((I) & 3) * SSTR;                                   \
        cpa16(sb + arow * 80 + ac8 * 2,               Ag  + acl + ac8);        \
        cpa16(sb + 5120 + arow * 80 + ac8 * 2,        Bg0 + bcl + ac8);        \
        cpa16(sb + 5120 + (64 + arow) * 80 + ac8 * 2, Bg1 + bcl + ac8);        \
        asm volatile("cp.async.commit_group;\n" ::);                           \
    }

    ISSUE_G(0) ISSUE_G(1) ISSUE_G(2)

    for (int i = 0; i < nk; i++) {
        const int st = i & 3;
        const int rem = nk - 1 - i;
        if (rem >= 2)      asm volatile("cp.async.wait_group 2;\n" ::);
        else if (rem == 1) asm volatile("cp.async.wait_group 1;\n" ::);
        else               asm volatile("cp.async.wait_group 0;\n" ::);
        __syncthreads();
        if (i + 3 < nk) ISSUE_G(i + 3)

        const uint32_t sa_base = su + st * SSTR;
        const uint32_t sb_base = sa_base + 5120;
#pragma unroll
        for (int ks = 0; ks < 2; ks++) {
            const int k0 = ks * 16;
            uint32_t a[2][4], b[4][2];
#pragma unroll
            for (int mi = 0; mi < 2; mi++) {
                uint32_t sa = sa_base + (wm * 32 + mi * 16 + (lane & 15)) * 80
                            + (k0 + (lane >> 4) * 8) * 2;
                asm volatile("ldmatrix.sync.aligned.m8n8.x4.shared.b16 {%0,%1,%2,%3}, [%4];"
                             : "=r"(a[mi][0]), "=r"(a[mi][1]), "=r"(a[mi][2]), "=r"(a[mi][3])
                             : "r"(sa));
            }
#pragma unroll
            for (int p = 0; p < 2; p++) {
                uint32_t sb = sb_base
                            + (wn * 32 + (2 * p + ((lane >> 4) & 1)) * 8 + (lane & 7)) * 80
                            + (k0 + ((lane >> 3) & 1) * 8) * 2;
                asm volatile("ldmatrix.sync.aligned.m8n8.x4.shared.b16 {%0,%1,%2,%3}, [%4];"
                             : "=r"(b[2 * p][0]), "=r"(b[2 * p][1]),
                               "=r"(b[2 * p + 1][0]), "=r"(b[2 * p + 1][1])
                             : "r"(sb));
            }
#pragma unroll
            for (int mi = 0; mi < 2; mi++)
#pragma unroll
                for (int ni = 0; ni < 4; ni++) {
                    asm volatile(
                        "mma.sync.aligned.m16n8k16.row.col.f32.bf16.bf16.f32 "
                        "{%0,%1,%2,%3}, {%4,%5,%6,%7}, {%8,%9}, {%0,%1,%2,%3};"
                        : "+f"(acc[mi][ni][0]), "+f"(acc[mi][ni][1]),
                          "+f"(acc[mi][ni][2]), "+f"(acc[mi][ni][3])
                        : "r"(a[mi][0]), "r"(a[mi][1]), "r"(a[mi][2]), "r"(a[mi][3]),
                          "r"(b[ni][0]), "r"(b[ni][1]));
                }
        }
    }
#undef ISSUE_G

    const int rbase = bm * 64 + wm * 32;
    const int cbase = bn * 128 + wn * 32;
    const float* bias = cg.bias;

    float* C = (float*)cg.Cv;
    const int ldc = cg.ldc;
#pragma unroll
    for (int mi = 0; mi < 2; mi++)
#pragma unroll
        for (int ni = 0; ni < 4; ni++) {
            int r0 = rbase + mi * 16 + (lane >> 2);
            int c0 = cbase + ni * 8 + (lane & 3) * 2;
            float b0 = bias[c0], b1 = bias[c0 + 1];
            float2 o0 = make_float2(acc[mi][ni][0] + b0, acc[mi][ni][1] + b1);
            float2 o1 = make_float2(acc[mi][ni][2] + b0, acc[mi][ni][3] + b1);
            *(float2*)(C + (size_t)r0 * ldc + c0) = o0;
            *(float2*)(C + (size_t)(r0 + 8) * ldc + c0) = o1;
        }
}

// ====== specialized D-GEMM (R14 4-warp kernel, optional split-K) =========
// MODE 0: NKT=54, grid.z=2, fp32 partial to (z?C1:C0), bias only on z==0.
// MODE 1: NKT=108, grid.z=1, softplus -> packed bf16 [hi|hi|lo] into Cv.
template <int MODE, int NKT>
__global__ void __launch_bounds__(128) dgemm(
    const bf16* __restrict__ A, const bf16* __restrict__ B,
    const float* __restrict__ bias, void* __restrict__ Cv,
    float* __restrict__ C1, int ldc)
{
    constexpr int K = 1152, LD = 3456;

    extern __shared__ __align__(16) char smraw[];
    const uint32_t su = (uint32_t)__cvta_generic_to_shared(smraw);

    const int tid = threadIdx.x, lane = tid & 31;
    const int wn = tid >> 5;
    const int bm = blockIdx.y, bn = blockIdx.x, bz = blockIdx.z;
    const int kbase = bz * (NKT * 32);

    const int arow = tid >> 2, ac8 = (tid & 3) * 8;
    const bf16* Ag = A + (size_t)(bm * 64 + arow) * LD + ac8 + kbase;
    const bf16* Bg = B + (size_t)(bn * 128 + arow) * LD + ac8 + kbase;

    float acc[4][4][4];
#pragma unroll
    for (int i = 0; i < 4; i++)
#pragma unroll
        for (int j = 0; j < 4; j++)
#pragma unroll
            for (int q = 0; q < 4; q++) acc[i][j][q] = 0.f;

#define ISSUE_D(I)                                                             \
    {                                                                          \
        int kk = (I) * 32;                                                     \
        uint32_t sb = su + ((I) & 3) * SSTR;                                   \
        _Pragma("unroll")                                                      \
        for (int p = 0; p < 2; p++)                                            \
            cpa16(sb + (p * 32 + arow) * 80 + ac8 * 2,                         \
                  Ag + (size_t)(p * 32) * LD + kk);                            \
        _Pragma("unroll")                                                      \
        for (int p = 0; p < 4; p++)                                            \
            cpa16(sb + 5120 + (p * 32 + arow) * 80 + ac8 * 2,                  \
                  Bg + (size_t)(p * 32) * LD + kk);                            \
        asm volatile("cp.async.commit_group;\n" ::);                           \
    }

#define COMPUTE_D(I)                                                           \
    {                                                                          \
        const uint32_t sa_base = su + ((I) & 3) * SSTR;                        \
        const uint32_t sb_base = sa_base + 5120;                               \
        _Pragma("unroll")                                                      \
        for (int ks = 0; ks < 2; ks++) {                                       \
            const int k0 = ks * 16;                                            \
            uint32_t a[4][4], b[4][2];                                         \
            _Pragma("unroll")                                                  \
            for (int mi = 0; mi < 4; mi++) {                                   \
                uint32_t sa = sa_base + (mi * 16 + (lane & 15)) * 80           \
                            + (k0 + (lane >> 4) * 8) * 2;                      \
                asm volatile(                                                  \
                    "ldmatrix.sync.aligned.m8n8.x4.shared.b16 {%0,%1,%2,%3}, [%4];" \
                    : "=r"(a[mi][0]), "=r"(a[mi][1]), "=r"(a[mi][2]), "=r"(a[mi][3]) \
                    : "r"(sa));                                                \
            }                                                                  \
            _Pragma("unroll")                                                  \
            for (int p = 0; p < 2; p++) {                                      \
                uint32_t sb = sb_base                                          \
                    + (wn * 32 + (2 * p + ((lane >> 4) & 1)) * 8 + (lane & 7)) * 80 \
                    + (k0 + ((lane >> 3) & 1) * 8) * 2;                        \
                asm volatile(                                                  \
                    "ldmatrix.sync.aligned.m8n8.x4.shared.b16 {%0,%1,%2,%3}, [%4];" \
                    : "=r"(b[2 * p][0]), "=r"(b[2 * p][1]),                    \
                      "=r"(b[2 * p + 1][0]), "=r"(b[2 * p + 1][1])             \
                    : "r"(sb));                                                \
            }                                                                  \
            _Pragma("unroll")                                                  \
            for (int mi = 0; mi < 4; mi++)                                     \
                _Pragma("unroll")                                              \
                for (int ni = 0; ni < 4; ni++) {                               \
                    asm volatile(                                              \
                        "mma.sync.aligned.m16n8k16.row.col.f32.bf16.bf16.f32 " \
                        "{%0,%1,%2,%3}, {%4,%5,%6,%7}, {%8,%9}, {%0,%1,%2,%3};"\
                        : "+f"(acc[mi][ni][0]), "+f"(acc[mi][ni][1]),          \
                          "+f"(acc[mi][ni][2]), "+f"(acc[mi][ni][3])           \
                        : "r"(a[mi][0]), "r"(a[mi][1]), "r"(a[mi][2]), "r"(a[mi][3]), \
                          "r"(b[ni][0]), "r"(b[ni][1]));                       \
                }                                                              \
        }                                                                      \
    }

    ISSUE_D(0) ISSUE_D(1) ISSUE_D(2)

#pragma unroll 4
    for (int i = 0; i < NKT - 3; i++) {
        asm volatile("cp.async.wait_group 2;\n" ::);
        __syncthreads();
        ISSUE_D(i + 3)
        COMPUTE_D(i)
    }
    asm volatile("cp.async.wait_group 2;\n" ::);
    __syncthreads();
    COMPUTE_D(NKT - 3)
    asm volatile("cp.async.wait_group 1;\n" ::);
    __syncthreads();
    COMPUTE_D(NKT - 2)
    asm volatile("cp.async.wait_group 0;\n" ::);
    __syncthreads();
    COMPUTE_D(NKT - 1)

#undef ISSUE_D
#undef COMPUTE_D

    const int cbase = bn * 128 + wn * 32;

    if (MODE == 0) {
        float* C = (bz == 0) ? (float*)Cv : C1;
#pragma unroll
        for (int mi = 0; mi < 4; mi++)
#pragma unroll
            for (int ni = 0; ni < 4; ni++) {
                int r0 = bm * 64 + mi * 16 + (lane >> 2);
                int c0 = cbase + ni * 8 + (lane & 3) * 2;
                float b0 = (bz == 0) ? bias[c0]     : 0.f;
                float b1 = (bz == 0) ? bias[c0 + 1] : 0.f;
                float2 o0 = make_float2(acc[mi][ni][0] + b0, acc[mi][ni][1] + b1);
                float2 o1 = make_float2(acc[mi][ni][2] + b0, acc[mi][ni][3] + b1);
                *(float2*)(C + (size_t)r0 * ldc + c0) = o0;
                *(float2*)(C + (size_t)(r0 + 8) * ldc + c0) = o1;
            }
    } else {
        bf16* C = (bf16*)Cv;  // packed, row stride 3456
#pragma unroll
        for (int mi = 0; mi < 4; mi++)
#pragma unroll
            for (int ni = 0; ni < 4; ni++) {
                int r0 = bm * 64 + mi * 16 + (lane >> 2);
                int c0 = cbase + ni * 8 + (lane & 3) * 2;
                float b0 = bias[c0], b1 = bias[c0 + 1];
#pragma unroll
                for (int h = 0; h < 2; h++) {
                    float v0 = splus(acc[mi][ni][2 * h + 0] + b0);
                    float v1 = splus(acc[mi][ni][2 * h + 1] + b1);
                    bf16 h0 = __float2bfloat16(v0), h1 = __float2bfloat16(v1);
                    bf16 l0 = __float2bfloat16(v0 - __bfloat162float(h0));
                    bf16 l1 = __float2bfloat16(v1 - __bfloat162float(h1));
                    bf162 hh; hh.x = h0; hh.y = h1;
                    bf162 ll; ll.x = l0; ll.y = l1;
                    bf16* base = C + (size_t)(r0 + 8 * h) * 3456 + c0;
                    *(bf162*)(base)         = hh;
                    *(bf162*)(base + K)     = hh;
                    *(bf162*)(base + 2 * K) = ll;
                }
            }
    }
}

// ---------------- single fused weight pack (B-side: [hi | lo | hi]) ------
__device__ __forceinline__ void packW_el(const float* in, bf16* out, int idx, int K)
{
    int n = idx / K, k = idx % K;
    float v = in[(size_t)n * K + k];
    bf16 hi = __float2bfloat16(v);
    bf16 lo = __float2bfloat16(v - __bfloat162float(hi));
    bf16* o = out + (size_t)n * 3 * K;
    o[k] = hi; o[K + k] = lo; o[2 * K + k] = hi;
}

#define S0 (G3 * 256)
#define S1B (S0 + G3 * 512)
#define S2B (S1B + G3 * 128)
#define S3B (S2B + G3 * 512)
#define S4B (S3B + Dd * Dd)
#define S5B (S4B + Dd * Dd)

__global__ void packAll_k(const float* __restrict__ Wiha, const float* __restrict__ Whha,
                          const float* __restrict__ Wihx, const float* __restrict__ Whhx,
                          const float* __restrict__ W1,   const float* __restrict__ W2)
{
    int idx = blockIdx.x * blockDim.x + threadIdx.x;
    if (idx >= S5B) return;
    if (idx < S0)       packW_el(Wiha, pw_iha, idx,        256);
    else if (idx < S1B) packW_el(Whha, pw_hha, idx - S0,   512);
    else if (idx < S2B) packW_el(Wihx, pw_ihx, idx - S1B,  128);
    else if (idx < S3B) packW_el(Whhx, pw_hhx, idx - S2B,  512);
    else if (idx < S4B) packW_el(W1,   pw_1,   idx - S3B,  Dd);
    else                packW_el(W2,   pw_2,   idx - S4B,  Dd);
}

// ---------------- elementwise (R14-proven forms) ----------------
__global__ void init_k(const float* __restrict__ x, float* __restrict__ out_x,
                       float* __restrict__ out_za)
{
    int idx = blockIdx.x * blockDim.x + threadIdx.x;
    if (idx >= Bb * Dd) return;
    int b = idx / Dd, j = idx % Dd;
    float v;
    if (j < 1024) {
        v = 0.0f;
        if (j < AHd) out_za[((size_t)b * Tt) * AHd + j] = 0.0f;
    } else {
        v = x[((size_t)b * Tt) * Xs + (j - 1024)];
        out_x[((size_t)b * Tt) * Xs + (j - 1024)] = v;
    }
    g_s[idx] = v;
    packA_el(pk_s + (size_t)b * 3 * Dd, Dd, j, v);
}

__global__ void catmask_k(const float* __restrict__ y, int t)
{
    int b = blockIdx.x;
    int c = threadIdx.x;  // 128
    float yv = y[((size_t)b * Tt + t) * 128 + c];
    float xv = g_s[b * Dd + 1024 + c];
    bf16* rb = pk_cat + (size_t)b * 768;
    packA_el(rb, 256, c, xv);
    packA_el(rb, 256, 128 + c, yv);
    __shared__ float red[128];
    red[c] = yv;
    __syncthreads();
    for (int o = 64; o > 0; o >>= 1) {
        if (c < o) red[c] += red[c + o];
        __syncthreads();
    }
    if (c == 0) g_mask[b] = (red[0] != 0.0f) ? 1.0f : 0.0f;
}

__global__ void gru_k(float* __restrict__ out_za, int t)
{
    int idx = blockIdx.x * blockDim.x + threadIdx.x;
    if (idx >= Bb * 1024) return;
    int b = idx >> 10, j = idx & 1023;
    if (j < XHd) {
        const float* gi = g_gix + (size_t)b * G3;
        const float* gh = g_ghx + (size_t)b * G3;
        float r = sigm(gi[j] + gh[j]);
        float z = sigm(gi[XHd + j] + gh[XHd + j]);
        float n = tanhf(gi[2 * XHd + j] + r * gh[2 * XHd + j]);
        float h = g_s[b * Dd + j];
        float v = (1.0f - z) * n + z * h;
        g_s[b * Dd + j] = v;
        packA_el(pk_s + (size_t)b * 3 * Dd, Dd, j, v);
    } else {
        int ja = j - XHd;
        const float* gi = g_gia + (size_t)b * G3;
        const float* gh = g_gha + (size_t)b * G3;
        float r = sigm(gi[ja] + gh[ja]);
        float z = sigm(gi[AHd + ja] + gh[AHd + ja]);
        float n = tanhf(gi[2 * AHd + ja] + r * gh[2 * AHd + ja]);
        float h = g_s[b * Dd + XHd + ja];
        float hn = (1.0f - z) * n + z * h;
        float v = (g_mask[b] != 0.0f) ? hn : h;
        g_s[b * Dd + XHd + ja] = v;
        packA_el(pk_s + (size_t)b * 3 * Dd, Dd, XHd + ja, v);
        out_za[((size_t)b * Tt + t + 1) * AHd + ja] = v;
    }
}

// RK combines: k value = pa + pb (split-K partials; R13-proven)
__global__ void rk_c1(const float* __restrict__ ts, int t)
{
    int i = blockIdx.x * blockDim.x + threadIdx.x;
    if (i >= Bb * Dd) return;
    float dt = ts[t + 1] - ts[t];
    int b = i / Dd, j = i % Dd;
    float kv = g_pa[i] + g_pb[i];
    g_k1[i] = kv;
    float v = g_s[i] + (dt * (1.0f / 3.0f)) * kv;
    packA_el(pk_s + (size_t)b * 3 * Dd, Dd, j, v);
}
__global__ void rk_c2(const float* __restrict__ ts, int t)
{
    int i = blockIdx.x * blockDim.x + threadIdx.x;
    if (i >= Bb * Dd) return;
    float dt = ts[t + 1] - ts[t];
    int b = i / Dd, j = i % Dd;
    float k1 = g_k1[i];
    float k2 = g_pa[i] + g_pb[i];
    g_k2[i] = k2;
    float v = g_s[i] + dt * (k2 - k1 * (1.0f / 3.0f));
    g_accb[i] = k1 + 3.0f * k2;
    packA_el(pk_s + (size_t)b * 3 * Dd, Dd, j, v);
}
__global__ void rk_c3(const float* __restrict__ ts, int t)
{
    int i = blockIdx.x * blockDim.x + threadIdx.x;
    if (i >= Bb * Dd) return;
    float dt = ts[t + 1] - ts[t];
    int b = i / Dd, j = i % Dd;
    float k1 = g_k1[i], k2 = g_k2[i];
    float k3 = g_pa[i] + g_pb[i];
    float v = g_s[i] + dt * (k1 - k2 + k3);
    g_accb[i] = g_accb[i] + 3.0f * k3;
    packA_el(pk_s + (size_t)b * 3 * Dd, Dd, j, v);
}
__global__ void rk_c4(const float* __restrict__ ts, float* __restrict__ out_x, int t)
{
    int i = blockIdx.x * blockDim.x + threadIdx.x;
    if (i >= Bb * Dd) return;
    float dt = ts[t + 1] - ts[t];
    int b = i / Dd, j = i % Dd;
    float k4 = g_pa[i] + g_pb[i];
    float v = g_s[i] + (dt * 0.125f) * (g_accb[i] + k4);
    g_s[i] = v;
    packA_el(pk_s + (size_t)b * 3 * Dd, Dd, j, v);
    if (j >= 1024)
        out_x[((size_t)b * Tt + t + 1) * Xs + (j - 1024)] = v;
}

// ---------------- host ----------------
static inline Cfg mkcfg(const bf16* A, int lda, int segA,
                        const bf16* B, int ldb, int segB,
                        const float* bias, void* C, int ldc, int K, int mode)
{
    Cfg c; c.A = A; c.B = B; c.bias = bias; c.Cv = C;
    c.lda = lda; c.segA = segA; c.ldb = ldb; c.segB = segB;
    c.ldc = ldc; c.K = K; c.mode = mode;
    return c;
}

extern "C" void kernel_launch(void* const* d_in, const int* in_sizes, int n_in,
                              void* d_out, int out_size)
{
    const float* x    = (const float*)d_in[0];
    const float* y    = (const float*)d_in[1];
    const float* ts   = (const float*)d_in[2];
    const float* Wiha = (const float*)d_in[3];
    const float* Whha = (const float*)d_in[4];
    const float* biha = (const float*)d_in[5];
    const float* bhha = (const float*)d_in[6];
    const float* Wihx = (const float*)d_in[7];
    const float* Whhx = (const float*)d_in[8];
    const float* bihx = (const float*)d_in[9];
    const float* bhhx = (const float*)d_in[10];
    const float* W1   = (const float*)d_in[11];
    const float* b1   = (const float*)d_in[12];
    const float* W2   = (const float*)d_in[13];
    const float* b2   = (const float*)d_in[14];

    float* out_x  = (float*)d_out;
    float* out_za = out_x + (size_t)Bb * Tt * Xs;

    cudaFuncSetAttribute(gemm_bf16,      cudaFuncAttributeMaxDynamicSharedMemorySize, SMEM_SZ);
    cudaFuncSetAttribute((dgemm<0, 54>),  cudaFuncAttributeMaxDynamicSharedMemorySize, SMEM_SZ);
    cudaFuncSetAttribute((dgemm<1, 108>), cudaFuncAttributeMaxDynamicSharedMemorySize, SMEM_SZ);

    bf16 *p_s, *p_cat, *p_h, *p_iha, *p_hha, *p_ihx, *p_hhx, *p_w1, *p_w2;
    float *pgia, *pgha, *pgix, *pghx, *ppa, *ppb;
    cudaGetSymbolAddress((void**)&p_s,   pk_s);
    cudaGetSymbolAddress((void**)&p_cat, pk_cat);
    cudaGetSymbolAddress((void**)&p_h,   pk_h);
    cudaGetSymbolAddress((void**)&p_iha, pw_iha);
    cudaGetSymbolAddress((void**)&p_hha, pw_hha);
    cudaGetSymbolAddress((void**)&p_ihx, pw_ihx);
    cudaGetSymbolAddress((void**)&p_hhx, pw_hhx);
    cudaGetSymbolAddress((void**)&p_w1,  pw_1);
    cudaGetSymbolAddress((void**)&p_w2,  pw_2);
    cudaGetSymbolAddress((void**)&pgia,  g_gia);
    cudaGetSymbolAddress((void**)&pgha,  g_gha);
    cudaGetSymbolAddress((void**)&pgix,  g_gix);
    cudaGetSymbolAddress((void**)&pghx,  g_ghx);
    cudaGetSymbolAddress((void**)&ppa,   g_pa);
    cudaGetSymbolAddress((void**)&ppb,   g_pb);

    packAll_k<<<(S5B + 255) / 256, 256>>>(Wiha, Whha, Wihx, Whhx, W1, W2);

    const int blkBD = (Bb * Dd + 255) / 256;
    const int blkG  = (Bb * 1024 + 255) / 256;

    init_k<<<blkBD, 256>>>(x, out_x, out_za);

    const dim3 gridGate(G3 / 128, Bb / 64, 4);
    const dim3 gridD1(Dd / 128, Bb / 64, 1);   // 9x16,  softplus GEMM
    const dim3 gridD2(Dd / 128, Bb / 64, 2);   // 9x16x2 split-K W2 GEMM

    for (int t = 0; t < NSTEP; t++) {
        catmask_k<<<Bb, 128>>>(y, t);

        Cfg4 G;
        G.c[0] = mkcfg(p_s + XHd,   3456, 1152, p_hha, 1536, 512, bhha, pgha, G3, 512, 0);
        G.c[1] = mkcfg(p_s,         3456, 1152, p_hhx, 1536, 512, bhhx, pghx, G3, 512, 0);
        G.c[2] = mkcfg(p_cat,        768, 256,  p_iha, 768,  256, biha, pgia, G3, 256, 0);
        G.c[3] = mkcfg(p_s + 1024,  3456, 1152, p_ihx, 384,  128, bihx, pgix, G3, 128, 0);
        gemm_bf16<<<gridGate, 256, SMEM_SZ>>>(G);

        gru_k<<<blkG, 256>>>(out_za, t);

        for (int q = 0; q < 4; q++) {
            dgemm<1, 108><<<gridD1, 128, SMEM_SZ>>>(p_s, p_w1, b1, p_h, nullptr, 0);
            dgemm<0, 54><<<gridD2, 128, SMEM_SZ>>>(p_h, p_w2, b2, ppa, ppb, Dd);
            if (q == 0)      rk_c1<<<blkBD, 256>>>(ts, t);
            else if (q == 1) rk_c2<<<blkBD, 256>>>(ts, t);
            else if (q == 2) rk_c3<<<blkBD, 256>>>(ts, t);
            else             rk_c4<<<blkBD, 256>>>(ts, out_x, t);
        }
    }
}